// round 1
// baseline (speedup 1.0000x reference)
#include <cuda_runtime.h>
#include <cstdint>

// UniAttention: O = softmax(Q K^T + mask) V
// B=16, LQ=LK=2048, D=1024, fp32.
// Staged: (1) S = Q K^T with key_len mask fused -> g_S scratch
//         (2) row softmax in-place on g_S
//         (3) O = P V
// All dims are multiples of the tile sizes; no bounds checks needed.

#define NEG_INF (-3.402823466e38f)

constexpr int Bc  = 16;
constexpr int LQc = 2048;
constexpr int LKc = 2048;
constexpr int Dc  = 1024;

constexpr int BM = 128, BN = 128, BK = 16;
constexpr int PADA = 4;  // pad transposed-A/B smem rows to dodge store conflicts

// 16*2048*2048 fp32 = 268 MB scratch for S / P (static device array: allowed)
__device__ float g_S[(size_t)Bc * LQc * LKc];

// ---------------------------------------------------------------------------
// Kernel 1: S[b][m][n] = sum_d Q[b][m][d] * K[b][n][d]; masked cols -> NEG_INF
// NT GEMM (both operands d-contiguous). 256 threads, 8x8 microtile.
// ---------------------------------------------------------------------------
__global__ __launch_bounds__(256, 2)
void qk_gemm(const float* __restrict__ Q, const float* __restrict__ Km,
             const int* __restrict__ key_len) {
    __shared__ float As[BK][BM + PADA];
    __shared__ float Bs[BK][BN + PADA];

    const int b = blockIdx.z;
    const float* A    = Q  + (size_t)b * LQc * Dc;
    const float* Bmat = Km + (size_t)b * LKc * Dc;
    float*       C    = g_S + (size_t)b * LQc * LKc;

    const int tid = threadIdx.x;
    const int m0 = blockIdx.y * BM;
    const int n0 = blockIdx.x * BN;

    // global->smem (transpose) mapping: 64 rows x 16 d per pass, float4 loads
    const int lrow = tid >> 2;          // 0..63
    const int lcol = (tid & 3) << 2;    // 0,4,8,12

    // compute mapping: 16x16 thread grid, each owns 8x8 of the 128x128 tile
    const int ty = tid >> 4;            // 0..15
    const int tx = tid & 15;            // 0..15

    float acc[8][8];
#pragma unroll
    for (int i = 0; i < 8; i++)
#pragma unroll
        for (int j = 0; j < 8; j++) acc[i][j] = 0.0f;

    for (int k0 = 0; k0 < Dc; k0 += BK) {
#pragma unroll
        for (int r = 0; r < BM; r += 64) {
            float4 v = *(const float4*)(A + (size_t)(m0 + lrow + r) * Dc + k0 + lcol);
            As[lcol + 0][lrow + r] = v.x;
            As[lcol + 1][lrow + r] = v.y;
            As[lcol + 2][lrow + r] = v.z;
            As[lcol + 3][lrow + r] = v.w;
        }
#pragma unroll
        for (int r = 0; r < BN; r += 64) {
            float4 v = *(const float4*)(Bmat + (size_t)(n0 + lrow + r) * Dc + k0 + lcol);
            Bs[lcol + 0][lrow + r] = v.x;
            Bs[lcol + 1][lrow + r] = v.y;
            Bs[lcol + 2][lrow + r] = v.z;
            Bs[lcol + 3][lrow + r] = v.w;
        }
        __syncthreads();
#pragma unroll
        for (int kk = 0; kk < BK; kk++) {
            float a[8], bb[8];
            *(float4*)&a[0]  = *(const float4*)&As[kk][ty * 8];
            *(float4*)&a[4]  = *(const float4*)&As[kk][ty * 8 + 4];
            *(float4*)&bb[0] = *(const float4*)&Bs[kk][tx * 8];
            *(float4*)&bb[4] = *(const float4*)&Bs[kk][tx * 8 + 4];
#pragma unroll
            for (int i = 0; i < 8; i++)
#pragma unroll
                for (int j = 0; j < 8; j++)
                    acc[i][j] += a[i] * bb[j];
        }
        __syncthreads();
    }

    const int klen = key_len[b];
#pragma unroll
    for (int i = 0; i < 8; i++) {
        const int m = m0 + ty * 8 + i;
#pragma unroll
        for (int jc = 0; jc < 8; jc += 4) {
            const int n = n0 + tx * 8 + jc;
            float4 v;
            v.x = (n + 0 < klen) ? acc[i][jc + 0] : NEG_INF;
            v.y = (n + 1 < klen) ? acc[i][jc + 1] : NEG_INF;
            v.z = (n + 2 < klen) ? acc[i][jc + 2] : NEG_INF;
            v.w = (n + 3 < klen) ? acc[i][jc + 3] : NEG_INF;
            *(float4*)(C + (size_t)m * LKc + n) = v;
        }
    }
}

// ---------------------------------------------------------------------------
// Kernel 2: in-place row softmax over LK=2048. One block per (q, b) row.
// key_len==0 rows are all NEG_INF -> m=NEG_INF -> exp(0)=1 -> uniform 1/2048,
// exactly matching the reference semantics.
// ---------------------------------------------------------------------------
__global__ __launch_bounds__(256)
void softmax_rows() {
    const int q = blockIdx.x;
    const int b = blockIdx.y;
    float* row = g_S + ((size_t)b * LQc + q) * LKc;
    const int tid = threadIdx.x;

    __shared__ float red[8];

    float vals[8];
    float m = NEG_INF;
#pragma unroll
    for (int i = 0; i < 8; i++) {
        vals[i] = row[tid + i * 256];
        m = fmaxf(m, vals[i]);
    }
#pragma unroll
    for (int off = 16; off > 0; off >>= 1)
        m = fmaxf(m, __shfl_xor_sync(0xffffffffu, m, off));
    if ((tid & 31) == 0) red[tid >> 5] = m;
    __syncthreads();
    float mfull = red[0];
#pragma unroll
    for (int w = 1; w < 8; w++) mfull = fmaxf(mfull, red[w]);
    __syncthreads();  // everyone done reading red before reuse

    float s = 0.0f;
#pragma unroll
    for (int i = 0; i < 8; i++) {
        vals[i] = expf(vals[i] - mfull);
        s += vals[i];
    }
#pragma unroll
    for (int off = 16; off > 0; off >>= 1)
        s += __shfl_xor_sync(0xffffffffu, s, off);
    if ((tid & 31) == 0) red[tid >> 5] = s;
    __syncthreads();
    float total = 0.0f;
#pragma unroll
    for (int w = 0; w < 8; w++) total += red[w];

    const float inv = 1.0f / total;
#pragma unroll
    for (int i = 0; i < 8; i++)
        row[tid + i * 256] = vals[i] * inv;
}

// ---------------------------------------------------------------------------
// Kernel 3: O[b][m][v] = sum_k P[b][m][k] * V[b][k][v]  (NN GEMM)
// ---------------------------------------------------------------------------
__global__ __launch_bounds__(256, 2)
void pv_gemm(const float* __restrict__ V, float* __restrict__ Out) {
    __shared__ float As[BK][BM + PADA];
    __shared__ float Bs[BK][BN];

    const int b = blockIdx.z;
    const float* P  = g_S + (size_t)b * LQc * LKc;
    const float* Vb = V   + (size_t)b * LKc * Dc;
    float*       C  = Out + (size_t)b * LQc * Dc;

    const int tid = threadIdx.x;
    const int m0 = blockIdx.y * BM;
    const int n0 = blockIdx.x * BN;

    // A (P) transpose-load mapping
    const int lrow = tid >> 2;          // 0..63
    const int lcol = (tid & 3) << 2;    // 0,4,8,12
    // B (V) natural-load mapping: 8 k-rows x 128 cols per pass
    const int brow = tid >> 5;          // 0..7
    const int bcol = (tid & 31) << 2;   // 0..124

    const int ty = tid >> 4;
    const int tx = tid & 15;

    float acc[8][8];
#pragma unroll
    for (int i = 0; i < 8; i++)
#pragma unroll
        for (int j = 0; j < 8; j++) acc[i][j] = 0.0f;

    for (int k0 = 0; k0 < LKc; k0 += BK) {
#pragma unroll
        for (int r = 0; r < BM; r += 64) {
            float4 v = *(const float4*)(P + (size_t)(m0 + lrow + r) * LKc + k0 + lcol);
            As[lcol + 0][lrow + r] = v.x;
            As[lcol + 1][lrow + r] = v.y;
            As[lcol + 2][lrow + r] = v.z;
            As[lcol + 3][lrow + r] = v.w;
        }
#pragma unroll
        for (int r = 0; r < BK; r += 8) {
            *(float4*)&Bs[brow + r][bcol] =
                *(const float4*)(Vb + (size_t)(k0 + brow + r) * Dc + n0 + bcol);
        }
        __syncthreads();
#pragma unroll
        for (int kk = 0; kk < BK; kk++) {
            float a[8], bb[8];
            *(float4*)&a[0]  = *(const float4*)&As[kk][ty * 8];
            *(float4*)&a[4]  = *(const float4*)&As[kk][ty * 8 + 4];
            *(float4*)&bb[0] = *(const float4*)&Bs[kk][tx * 8];
            *(float4*)&bb[4] = *(const float4*)&Bs[kk][tx * 8 + 4];
#pragma unroll
            for (int i = 0; i < 8; i++)
#pragma unroll
                for (int j = 0; j < 8; j++)
                    acc[i][j] += a[i] * bb[j];
        }
        __syncthreads();
    }

#pragma unroll
    for (int i = 0; i < 8; i++) {
        const int m = m0 + ty * 8 + i;
#pragma unroll
        for (int jc = 0; jc < 8; jc += 4) {
            float4 v;
            v.x = acc[i][jc + 0];
            v.y = acc[i][jc + 1];
            v.z = acc[i][jc + 2];
            v.w = acc[i][jc + 3];
            *(float4*)(C + (size_t)m * Dc + n0 + tx * 8 + jc) = v;
        }
    }
}

// ---------------------------------------------------------------------------
extern "C" void kernel_launch(void* const* d_in, const int* in_sizes, int n_in,
                              void* d_out, int out_size) {
    const float* Q      = (const float*)d_in[0];
    const float* K      = (const float*)d_in[1];
    const float* V      = (const float*)d_in[2];
    const int*  key_len = (const int*)d_in[3];
    float* Out = (float*)d_out;

    dim3 g1(LKc / BN, LQc / BM, Bc);   // (16, 16, 16)
    qk_gemm<<<g1, 256>>>(Q, K, key_len);

    dim3 g2(LQc, Bc);                  // (2048, 16)
    softmax_rows<<<g2, 256>>>();

    dim3 g3(Dc / BN, LQc / BM, Bc);    // (8, 16, 16)
    pv_gemm<<<g3, 256>>>(V, Out);
}

// round 6
// speedup vs baseline: 2.4276x; 2.4276x over previous
#include <cuda_runtime.h>
#include <cuda_bf16.h>
#include <cstdint>

#define NEG_INF (-3.402823466e38f)

constexpr int Bc = 16, LQ = 2048, LK = 2048, DD = 1024;

// Static device scratch (sanctioned alloc-free path)
__device__ float g_S[(size_t)Bc * LQ * LK];                                  // 268 MB
__device__ __nv_bfloat16 g_Qh[(size_t)Bc * LQ * DD], g_Ql[(size_t)Bc * LQ * DD];
__device__ __nv_bfloat16 g_Kh[(size_t)Bc * LK * DD], g_Kl[(size_t)Bc * LK * DD];
__device__ __nv_bfloat16 g_Vth[(size_t)Bc * DD * LK], g_Vtl[(size_t)Bc * DD * LK];
__device__ __nv_bfloat16 g_Ph[(size_t)Bc * LQ * LK], g_Pl[(size_t)Bc * LQ * LK];

// ---------------------------------------------------------------------------
// Base-ISA helpers (sm_103 WITHOUT 'a' features: mma.sync / ldmatrix / cp.async)
// ---------------------------------------------------------------------------
__device__ __forceinline__ uint32_t smem_u32(const void* p) {
    uint32_t a;
    asm("{ .reg .u64 t; cvta.to.shared.u64 t, %1; cvt.u32.u64 %0, t; }" : "=r"(a) : "l"(p));
    return a;
}
__device__ __forceinline__ void cpasync16(uint32_t dst, const void* src) {
    asm volatile("cp.async.cg.shared.global [%0], [%1], 16;" :: "r"(dst), "l"(src));
}
#define CP_COMMIT() asm volatile("cp.async.commit_group;" ::: "memory")
#define CP_WAIT1()  asm volatile("cp.async.wait_group 1;" ::: "memory")
#define CP_WAIT0()  asm volatile("cp.async.wait_group 0;" ::: "memory")

__device__ __forceinline__ void ldsm_x4(uint32_t* r, uint32_t addr) {
    asm volatile("ldmatrix.sync.aligned.m8n8.x4.shared.b16 {%0,%1,%2,%3}, [%4];"
                 : "=r"(r[0]), "=r"(r[1]), "=r"(r[2]), "=r"(r[3]) : "r"(addr));
}
__device__ __forceinline__ void mma16816(float* c, const uint32_t* a, const uint32_t* b) {
    asm volatile(
        "mma.sync.aligned.m16n8k16.row.col.f32.bf16.bf16.f32 "
        "{%0,%1,%2,%3}, {%4,%5,%6,%7}, {%8,%9}, {%0,%1,%2,%3};"
        : "+f"(c[0]), "+f"(c[1]), "+f"(c[2]), "+f"(c[3])
        : "r"(a[0]), "r"(a[1]), "r"(a[2]), "r"(a[3]), "r"(b[0]), "r"(b[1]));
}

// ---------------------------------------------------------------------------
// Prep: fp32 -> bf16 hi/lo split (elementwise). WHICH: 0=Q, 1=K
// ---------------------------------------------------------------------------
template <int WHICH>
__global__ __launch_bounds__(256)
void split_hl(const float4* __restrict__ in, int n4) {
    int i = blockIdx.x * 256 + threadIdx.x;
    if (i >= n4) return;
    __nv_bfloat16* hi = (WHICH == 0) ? g_Qh : g_Kh;
    __nv_bfloat16* lo = (WHICH == 0) ? g_Ql : g_Kl;
    float4 v = in[i];
    __nv_bfloat16 h0 = __float2bfloat16_rn(v.x), h1 = __float2bfloat16_rn(v.y),
                  h2 = __float2bfloat16_rn(v.z), h3 = __float2bfloat16_rn(v.w);
    __nv_bfloat16 l0 = __float2bfloat16_rn(v.x - __bfloat162float(h0));
    __nv_bfloat16 l1 = __float2bfloat16_rn(v.y - __bfloat162float(h1));
    __nv_bfloat16 l2 = __float2bfloat16_rn(v.z - __bfloat162float(h2));
    __nv_bfloat16 l3 = __float2bfloat16_rn(v.w - __bfloat162float(h3));
    __nv_bfloat162 ph0 = __halves2bfloat162(h0, h1), ph1 = __halves2bfloat162(h2, h3);
    __nv_bfloat162 pl0 = __halves2bfloat162(l0, l1), pl1 = __halves2bfloat162(l2, l3);
    *(uint2*)(hi + (size_t)i * 4) = make_uint2(*(uint32_t*)&ph0, *(uint32_t*)&ph1);
    *(uint2*)(lo + (size_t)i * 4) = make_uint2(*(uint32_t*)&pl0, *(uint32_t*)&pl1);
}

// ---------------------------------------------------------------------------
// Prep: V transpose + split:  g_Vt*[b][n][k] = split(V[b][k][n])
// ---------------------------------------------------------------------------
__global__ __launch_bounds__(256)
void transpose_split_v(const float* __restrict__ V) {
    __shared__ float t[32][33];
    const int b = blockIdx.z;
    const int n0 = blockIdx.x * 32, k0 = blockIdx.y * 32;
    const float* Vb = V + (size_t)b * LK * DD;
    for (int i = threadIdx.y; i < 32; i += 8)
        t[i][threadIdx.x] = Vb[(size_t)(k0 + i) * DD + n0 + threadIdx.x];
    __syncthreads();
    for (int i = threadIdx.y; i < 32; i += 8) {
        float v = t[threadIdx.x][i];   // = V[b][k0+tx][n0+i]
        __nv_bfloat16 h = __float2bfloat16_rn(v);
        __nv_bfloat16 l = __float2bfloat16_rn(v - __bfloat162float(h));
        size_t o = ((size_t)b * DD + n0 + i) * LK + k0 + threadIdx.x;
        g_Vth[o] = h;
        g_Vtl[o] = l;
    }
}

// ---------------------------------------------------------------------------
// Softmax over LK=2048, reading g_S, writing split P (bf16 hi/lo)
// ---------------------------------------------------------------------------
__global__ __launch_bounds__(256)
void softmax_split() {
    const int q = blockIdx.x, b = blockIdx.y;
    const size_t ro = ((size_t)b * LQ + q) * LK;
    const float* row = g_S + ro;
    const int tid = threadIdx.x;
    __shared__ float red[8];

    float vals[8];
    float m = NEG_INF;
#pragma unroll
    for (int i = 0; i < 8; i++) {
        vals[i] = row[tid + i * 256];
        m = fmaxf(m, vals[i]);
    }
#pragma unroll
    for (int off = 16; off > 0; off >>= 1)
        m = fmaxf(m, __shfl_xor_sync(0xffffffffu, m, off));
    if ((tid & 31) == 0) red[tid >> 5] = m;
    __syncthreads();
    float mf = red[0];
#pragma unroll
    for (int w = 1; w < 8; w++) mf = fmaxf(mf, red[w]);
    __syncthreads();

    float s = 0.0f;
#pragma unroll
    for (int i = 0; i < 8; i++) {
        vals[i] = expf(vals[i] - mf);
        s += vals[i];
    }
#pragma unroll
    for (int off = 16; off > 0; off >>= 1)
        s += __shfl_xor_sync(0xffffffffu, s, off);
    if ((tid & 31) == 0) red[tid >> 5] = s;
    __syncthreads();
    float tot = 0.0f;
#pragma unroll
    for (int w = 0; w < 8; w++) tot += red[w];

    const float inv = 1.0f / tot;
#pragma unroll
    for (int i = 0; i < 8; i++) {
        float p = vals[i] * inv;
        __nv_bfloat16 h = __float2bfloat16_rn(p);
        __nv_bfloat16 l = __float2bfloat16_rn(p - __bfloat162float(h));
        g_Ph[ro + tid + i * 256] = h;
        g_Pl[ro + tid + i * 256] = l;
    }
}

// ---------------------------------------------------------------------------
// GEMM on mma.sync: C[2048,NTOT] = A[2048,KDIM] * B[NTOT,KDIM]^T per batch.
// Operands pre-split bf16 hi/lo. 3-term: AhBh + AhBl + AlBh.
// WHICH=0: A=Qh/Ql, B=Kh/Kl, C=g_S, KDIM=1024, NTOT=2048, mask epilogue.
// WHICH=1: A=Ph/Pl, B=Vth/Vtl, C=Out,  KDIM=2048, NTOT=1024.
// CTA 128x128x64, 8 warps (2 M x 4 N), warp tile 64x32, 2-stage cp.async.
// SMEM: per stage 4 tiles (Ah,Al,Bh,Bl) of 128x64 bf16 = 64KB; 2 stages.
// ---------------------------------------------------------------------------
constexpr int SMEM_BYTES = 2 * 65536;

template <int KDIM>
__device__ __forceinline__ void load_stage_fn(
    uint32_t s0, const __nv_bfloat16* Ah, const __nv_bfloat16* Al,
    const __nv_bfloat16* Bh, const __nv_bfloat16* Bl, int k0, int tid) {
#pragma unroll
    for (int p = 0; p < 4; p++) {
        int lin = p * 256 + tid;
        int row = lin >> 3, ch = lin & 7;
        uint32_t d = s0 + (uint32_t)(row * 128) + (uint32_t)((ch ^ (row & 7)) << 4);
        size_t g = (size_t)row * KDIM + k0 + ch * 8;
        cpasync16(d,           Ah + g);
        cpasync16(d + 16384u,  Al + g);
        cpasync16(d + 32768u,  Bh + g);
        cpasync16(d + 49152u,  Bl + g);
    }
}

template <int WHICH>
__global__ __launch_bounds__(256, 1)
void gemm_mma(float* __restrict__ OutArg, const int* __restrict__ key_len) {
    constexpr int KDIM = (WHICH == 0) ? 1024 : 2048;
    constexpr int NTOT = (WHICH == 0) ? 2048 : 1024;
    constexpr bool MASK = (WHICH == 0);
    constexpr int KITERS = KDIM / 64;

    extern __shared__ __align__(1024) char sm[];
    const uint32_t sb = smem_u32(sm);

    const int tid = threadIdx.x, lane = tid & 31, warp = tid >> 5;
    const int wm = warp >> 2, wn = warp & 3;
    const int b = blockIdx.z, m0 = blockIdx.y * 128, n0 = blockIdx.x * 128;

    const __nv_bfloat16 *Ah, *Al, *Bh, *Bl;
    float* C;
    if (WHICH == 0) { Ah = g_Qh; Al = g_Ql; Bh = g_Kh; Bl = g_Kl; C = g_S; }
    else            { Ah = g_Ph; Al = g_Pl; Bh = g_Vth; Bl = g_Vtl; C = OutArg; }
    Ah += (size_t)b * 2048 * KDIM + (size_t)m0 * KDIM;
    Al += (size_t)b * 2048 * KDIM + (size_t)m0 * KDIM;
    Bh += (size_t)b * NTOT * KDIM + (size_t)n0 * KDIM;
    Bl += (size_t)b * NTOT * KDIM + (size_t)n0 * KDIM;
    C  += (size_t)b * 2048 * NTOT;

    float acc[4][4][4];
#pragma unroll
    for (int i = 0; i < 4; i++)
#pragma unroll
        for (int j = 0; j < 4; j++)
#pragma unroll
            for (int k = 0; k < 4; k++) acc[i][j][k] = 0.0f;

    // ldmatrix per-lane address components (row&7 == lane&7 since tiles 16-aligned)
    const int lrow = lane & 7, sub = lane >> 3;
    const uint32_t roff = (uint32_t)((lrow + ((sub & 1) << 3)) << 7);
    const int kx = sub >> 1;
    const int swz = lrow;

    load_stage_fn<KDIM>(sb, Ah, Al, Bh, Bl, 0, tid);
    CP_COMMIT();

    for (int it = 0; it < KITERS; ++it) {
        if (it + 1 < KITERS) {
            load_stage_fn<KDIM>(sb + ((it + 1) & 1) * 65536u, Ah, Al, Bh, Bl,
                                (it + 1) * 64, tid);
            CP_COMMIT();
            CP_WAIT1();
        } else {
            CP_WAIT0();
        }
        __syncthreads();

        const uint32_t aB = sb + (uint32_t)((it & 1) * 65536);
        const uint32_t bB = aB + 32768u;
#pragma unroll
        for (int ks = 0; ks < 4; ++ks) {
            const uint32_t ksw = (uint32_t)((((ks * 2 + kx) ^ swz)) << 4);
            uint32_t ah[4][4], al[4][4], bh[4][2], bl[4][2];
#pragma unroll
            for (int i = 0; i < 4; i++) {
                uint32_t ad = aB + ((uint32_t)(wm * 64 + i * 16) << 7) + roff + ksw;
                ldsm_x4(ah[i], ad);
                ldsm_x4(al[i], ad + 16384u);
            }
#pragma unroll
            for (int jp = 0; jp < 2; jp++) {
                uint32_t bd = bB + ((uint32_t)(wn * 32 + jp * 16) << 7) + roff + ksw;
                uint32_t t[4];
                ldsm_x4(t, bd);
                bh[jp * 2][0] = t[0]; bh[jp * 2][1] = t[2];
                bh[jp * 2 + 1][0] = t[1]; bh[jp * 2 + 1][1] = t[3];
                ldsm_x4(t, bd + 16384u);
                bl[jp * 2][0] = t[0]; bl[jp * 2][1] = t[2];
                bl[jp * 2 + 1][0] = t[1]; bl[jp * 2 + 1][1] = t[3];
            }
#pragma unroll
            for (int i = 0; i < 4; i++)
#pragma unroll
                for (int j = 0; j < 4; j++) {
                    mma16816(acc[i][j], ah[i], bh[j]);
                    mma16816(acc[i][j], ah[i], bl[j]);
                    mma16816(acc[i][j], al[i], bh[j]);
                }
        }
        __syncthreads();
    }

    // Epilogue: direct float2 stores (sector-aligned), mask for GEMM1
    const int klen = MASK ? key_len[b] : 0x7fffffff;
#pragma unroll
    for (int i = 0; i < 4; i++) {
        const int r = m0 + wm * 64 + i * 16 + (lane >> 2);
#pragma unroll
        for (int j = 0; j < 4; j++) {
            const int col = n0 + wn * 32 + j * 8 + ((lane & 3) << 1);
            float2 v0 = make_float2(acc[i][j][0], acc[i][j][1]);
            float2 v1 = make_float2(acc[i][j][2], acc[i][j][3]);
            if (MASK) {
                if (col     >= klen) { v0.x = NEG_INF; v1.x = NEG_INF; }
                if (col + 1 >= klen) { v0.y = NEG_INF; v1.y = NEG_INF; }
            }
            *(float2*)(C + (size_t)r * NTOT + col) = v0;
            *(float2*)(C + (size_t)(r + 8) * NTOT + col) = v1;
        }
    }
}

// ---------------------------------------------------------------------------
extern "C" void kernel_launch(void* const* d_in, const int* in_sizes, int n_in,
                              void* d_out, int out_size) {
    const float* Q      = (const float*)d_in[0];
    const float* K      = (const float*)d_in[1];
    const float* V      = (const float*)d_in[2];
    const int*  key_len = (const int*)d_in[3];
    float* Out = (float*)d_out;

    cudaFuncSetAttribute(gemm_mma<0>, cudaFuncAttributeMaxDynamicSharedMemorySize, SMEM_BYTES);
    cudaFuncSetAttribute(gemm_mma<1>, cudaFuncAttributeMaxDynamicSharedMemorySize, SMEM_BYTES);

    const int n4 = Bc * LQ * DD / 4;    // 8388608
    split_hl<0><<<(n4 + 255) / 256, 256>>>((const float4*)Q, n4);
    split_hl<1><<<(n4 + 255) / 256, 256>>>((const float4*)K, n4);

    dim3 gt(DD / 32, LK / 32, Bc);
    transpose_split_v<<<gt, dim3(32, 8)>>>(V);

    dim3 g1(LK / 128, LQ / 128, Bc);    // (16,16,16)
    gemm_mma<0><<<g1, 256, SMEM_BYTES>>>(nullptr, key_len);

    dim3 g2(LQ, Bc);
    softmax_split<<<g2, 256>>>();

    dim3 g3(DD / 128, LQ / 128, Bc);    // (8,16,16)
    gemm_mma<1><<<g3, 256, SMEM_BYTES>>>(Out, key_len);
}

// round 11
// speedup vs baseline: 4.3078x; 1.7745x over previous
#include <cuda_runtime.h>
#include <cuda_bf16.h>
#include <cstdint>

#define NEG_INF (-3.402823466e38f)

constexpr int Bc = 16, LQ = 2048, LK = 2048, DD = 1024;

// Static device scratch (sanctioned alloc-free path)
__device__ float g_S[(size_t)Bc * LQ * LK];                                  // 268 MB
__device__ __nv_bfloat16 g_Qh[(size_t)Bc * LQ * DD], g_Ql[(size_t)Bc * LQ * DD];
__device__ __nv_bfloat16 g_Kh[(size_t)Bc * LK * DD], g_Kl[(size_t)Bc * LK * DD];
__device__ __nv_bfloat16 g_Vth[(size_t)Bc * DD * LK], g_Vtl[(size_t)Bc * DD * LK];
__device__ __nv_bfloat16 g_Ph[(size_t)Bc * LQ * LK], g_Pl[(size_t)Bc * LQ * LK];

// ---------------------------------------------------------------------------
// Base-ISA helpers (mma.sync / ldmatrix / cp.async only — no 'a' features)
// ---------------------------------------------------------------------------
__device__ __forceinline__ uint32_t smem_u32(const void* p) {
    uint32_t a;
    asm("{ .reg .u64 t; cvta.to.shared.u64 t, %1; cvt.u32.u64 %0, t; }" : "=r"(a) : "l"(p));
    return a;
}
__device__ __forceinline__ void cpasync16(uint32_t dst, const void* src) {
    asm volatile("cp.async.cg.shared.global [%0], [%1], 16;" :: "r"(dst), "l"(src));
}
#define CP_COMMIT() asm volatile("cp.async.commit_group;" ::: "memory")
#define CP_WAIT1()  asm volatile("cp.async.wait_group 1;" ::: "memory")

__device__ __forceinline__ void ldsm_x4(uint32_t* r, uint32_t addr) {
    asm volatile("ldmatrix.sync.aligned.m8n8.x4.shared.b16 {%0,%1,%2,%3}, [%4];"
                 : "=r"(r[0]), "=r"(r[1]), "=r"(r[2]), "=r"(r[3]) : "r"(addr));
}
__device__ __forceinline__ void mma16816(float* c, const uint32_t* a, const uint32_t* b) {
    asm volatile(
        "mma.sync.aligned.m16n8k16.row.col.f32.bf16.bf16.f32 "
        "{%0,%1,%2,%3}, {%4,%5,%6,%7}, {%8,%9}, {%0,%1,%2,%3};"
        : "+f"(c[0]), "+f"(c[1]), "+f"(c[2]), "+f"(c[3])
        : "r"(a[0]), "r"(a[1]), "r"(a[2]), "r"(a[3]), "r"(b[0]), "r"(b[1]));
}

// ---------------------------------------------------------------------------
// Prep: fp32 -> bf16 hi/lo split (elementwise). WHICH: 0=Q, 1=K
// ---------------------------------------------------------------------------
template <int WHICH>
__global__ __launch_bounds__(256)
void split_hl(const float4* __restrict__ in, int n4) {
    int i = blockIdx.x * 256 + threadIdx.x;
    if (i >= n4) return;
    __nv_bfloat16* hi = (WHICH == 0) ? g_Qh : g_Kh;
    __nv_bfloat16* lo = (WHICH == 0) ? g_Ql : g_Kl;
    float4 v = in[i];
    __nv_bfloat16 h0 = __float2bfloat16_rn(v.x), h1 = __float2bfloat16_rn(v.y),
                  h2 = __float2bfloat16_rn(v.z), h3 = __float2bfloat16_rn(v.w);
    __nv_bfloat16 l0 = __float2bfloat16_rn(v.x - __bfloat162float(h0));
    __nv_bfloat16 l1 = __float2bfloat16_rn(v.y - __bfloat162float(h1));
    __nv_bfloat16 l2 = __float2bfloat16_rn(v.z - __bfloat162float(h2));
    __nv_bfloat16 l3 = __float2bfloat16_rn(v.w - __bfloat162float(h3));
    __nv_bfloat162 ph0 = __halves2bfloat162(h0, h1), ph1 = __halves2bfloat162(h2, h3);
    __nv_bfloat162 pl0 = __halves2bfloat162(l0, l1), pl1 = __halves2bfloat162(l2, l3);
    *(uint2*)(hi + (size_t)i * 4) = make_uint2(*(uint32_t*)&ph0, *(uint32_t*)&ph1);
    *(uint2*)(lo + (size_t)i * 4) = make_uint2(*(uint32_t*)&pl0, *(uint32_t*)&pl1);
}

// ---------------------------------------------------------------------------
// Prep: V transpose + split:  g_Vt*[b][n][k] = split(V[b][k][n])
// ---------------------------------------------------------------------------
__global__ __launch_bounds__(256)
void transpose_split_v(const float* __restrict__ V) {
    __shared__ float t[32][33];
    const int b = blockIdx.z;
    const int n0 = blockIdx.x * 32, k0 = blockIdx.y * 32;
    const float* Vb = V + (size_t)b * LK * DD;
    for (int i = threadIdx.y; i < 32; i += 8)
        t[i][threadIdx.x] = Vb[(size_t)(k0 + i) * DD + n0 + threadIdx.x];
    __syncthreads();
    for (int i = threadIdx.y; i < 32; i += 8) {
        float v = t[threadIdx.x][i];   // = V[b][k0+tx][n0+i]
        __nv_bfloat16 h = __float2bfloat16_rn(v);
        __nv_bfloat16 l = __float2bfloat16_rn(v - __bfloat162float(h));
        size_t o = ((size_t)b * DD + n0 + i) * LK + k0 + threadIdx.x;
        g_Vth[o] = h;
        g_Vtl[o] = l;
    }
}

// ---------------------------------------------------------------------------
// Softmax over LK=2048, reading g_S, writing split P (bf16 hi/lo)
// ---------------------------------------------------------------------------
__global__ __launch_bounds__(256)
void softmax_split() {
    const int q = blockIdx.x, b = blockIdx.y;
    const size_t ro = ((size_t)b * LQ + q) * LK;
    const float* row = g_S + ro;
    const int tid = threadIdx.x;
    __shared__ float red[8];

    float vals[8];
    float m = NEG_INF;
#pragma unroll
    for (int i = 0; i < 8; i++) {
        vals[i] = row[tid + i * 256];
        m = fmaxf(m, vals[i]);
    }
#pragma unroll
    for (int off = 16; off > 0; off >>= 1)
        m = fmaxf(m, __shfl_xor_sync(0xffffffffu, m, off));
    if ((tid & 31) == 0) red[tid >> 5] = m;
    __syncthreads();
    float mf = red[0];
#pragma unroll
    for (int w = 1; w < 8; w++) mf = fmaxf(mf, red[w]);
    __syncthreads();

    float s = 0.0f;
#pragma unroll
    for (int i = 0; i < 8; i++) {
        vals[i] = expf(vals[i] - mf);
        s += vals[i];
    }
#pragma unroll
    for (int off = 16; off > 0; off >>= 1)
        s += __shfl_xor_sync(0xffffffffu, s, off);
    if ((tid & 31) == 0) red[tid >> 5] = s;
    __syncthreads();
    float tot = 0.0f;
#pragma unroll
    for (int w = 0; w < 8; w++) tot += red[w];

    const float inv = 1.0f / tot;
#pragma unroll
    for (int i = 0; i < 8; i++) {
        float p = vals[i] * inv;
        __nv_bfloat16 h = __float2bfloat16_rn(p);
        __nv_bfloat16 l = __float2bfloat16_rn(p - __bfloat162float(h));
        g_Ph[ro + tid + i * 256] = h;
        g_Pl[ro + tid + i * 256] = l;
    }
}

// ---------------------------------------------------------------------------
// GEMM on mma.sync: C[2048,NTOT] = A[2048,KDIM] * B[NTOT,KDIM]^T per batch.
// Pre-split bf16 hi/lo, 3-term (AhBh + AhBl + AlBh).
// CTA 128x128x64, 8 warps (2Mx4N), warp tile 64x32.
// 3-stage cp.async pipeline (64KB/stage, 192KB), 1 syncthreads per K-iter.
// Fragment double-buffer across ks-steps; term-major MMA issue (RAW dist 16).
// key_len exploitation (bit-exact):
//   GEMM0: n0 >= klen -> whole tile is NEG_INF; skip mainloop entirely.
//   GEMM1: P columns >= klen are exactly 0 (exp underflow) when klen>0;
//          truncate K loop to ceil(klen/64) iters (klen==0 -> full range).
// ---------------------------------------------------------------------------
constexpr int STAGE_B = 65536;
constexpr int SMEM_BYTES = 3 * STAGE_B;   // 192 KB

template <int KDIM>
__device__ __forceinline__ void load_stage_fn(
    uint32_t s0, const __nv_bfloat16* Ah, const __nv_bfloat16* Al,
    const __nv_bfloat16* Bh, const __nv_bfloat16* Bl, int k0, int tid) {
#pragma unroll
    for (int p = 0; p < 4; p++) {
        int lin = p * 256 + tid;
        int row = lin >> 3, ch = lin & 7;
        uint32_t d = s0 + (uint32_t)(row * 128) + (uint32_t)((ch ^ (row & 7)) << 4);
        size_t g = (size_t)row * KDIM + k0 + ch * 8;
        cpasync16(d,           Ah + g);
        cpasync16(d + 16384u,  Al + g);
        cpasync16(d + 32768u,  Bh + g);
        cpasync16(d + 49152u,  Bl + g);
    }
}

struct Frags {
    uint32_t ah[4][4], al[4][4], bh[4][2], bl[4][2];
};

__device__ __forceinline__ void load_frags(
    Frags& f, uint32_t aB, uint32_t bB, int ks,
    uint32_t roff, int kx, int swz, int wm, int wn) {
    const uint32_t ksw = (uint32_t)((((ks * 2 + kx) ^ swz)) << 4);
#pragma unroll
    for (int i = 0; i < 4; i++) {
        uint32_t ad = aB + ((uint32_t)(wm * 64 + i * 16) << 7) + roff + ksw;
        ldsm_x4(f.ah[i], ad);
        ldsm_x4(f.al[i], ad + 16384u);
    }
#pragma unroll
    for (int jp = 0; jp < 2; jp++) {
        uint32_t bd = bB + ((uint32_t)(wn * 32 + jp * 16) << 7) + roff + ksw;
        uint32_t t[4];
        ldsm_x4(t, bd);
        f.bh[jp * 2][0] = t[0]; f.bh[jp * 2][1] = t[2];
        f.bh[jp * 2 + 1][0] = t[1]; f.bh[jp * 2 + 1][1] = t[3];
        ldsm_x4(t, bd + 16384u);
        f.bl[jp * 2][0] = t[0]; f.bl[jp * 2][1] = t[2];
        f.bl[jp * 2 + 1][0] = t[1]; f.bl[jp * 2 + 1][1] = t[3];
    }
}

// Term-major issue: all 16 acc tiles per term -> same-acc RAW distance = 16.
__device__ __forceinline__ void mma_all(float acc[4][4][4], const Frags& f) {
#pragma unroll
    for (int i = 0; i < 4; i++)
#pragma unroll
        for (int j = 0; j < 4; j++)
            mma16816(acc[i][j], f.ah[i], f.bh[j]);
#pragma unroll
    for (int i = 0; i < 4; i++)
#pragma unroll
        for (int j = 0; j < 4; j++)
            mma16816(acc[i][j], f.ah[i], f.bl[j]);
#pragma unroll
    for (int i = 0; i < 4; i++)
#pragma unroll
        for (int j = 0; j < 4; j++)
            mma16816(acc[i][j], f.al[i], f.bh[j]);
}

template <int WHICH>
__global__ __launch_bounds__(256, 1)
void gemm_mma(float* __restrict__ OutArg, const int* __restrict__ key_len) {
    constexpr int KDIM = (WHICH == 0) ? 1024 : 2048;
    constexpr int NTOT = (WHICH == 0) ? 2048 : 1024;
    constexpr bool MASK = (WHICH == 0);
    constexpr int KITERS = KDIM / 64;

    extern __shared__ __align__(1024) char sm[];
    const uint32_t sb = smem_u32(sm);

    const int tid = threadIdx.x, lane = tid & 31, warp = tid >> 5;
    const int wm = warp >> 2, wn = warp & 3;
    const int b = blockIdx.z, m0 = blockIdx.y * 128, n0 = blockIdx.x * 128;
    const int klen = key_len[b];

    const __nv_bfloat16 *Ah, *Al, *Bh, *Bl;
    float* C;
    if (WHICH == 0) { Ah = g_Qh; Al = g_Ql; Bh = g_Kh; Bl = g_Kl; C = g_S; }
    else            { Ah = g_Ph; Al = g_Pl; Bh = g_Vth; Bl = g_Vtl; C = OutArg; }
    C += (size_t)b * 2048 * NTOT;

    // GEMM0: fully-masked tile -> pure NEG_INF fill, no MMA work. Block-uniform.
    if (MASK && n0 >= klen) {
        const float4 nf = make_float4(NEG_INF, NEG_INF, NEG_INF, NEG_INF);
#pragma unroll
        for (int p = 0; p < 16; p++) {
            int idx = p * 256 + tid;          // 4096 float4s = 128x128
            int row = idx >> 5, c4 = idx & 31;
            *(float4*)(C + (size_t)(m0 + row) * NTOT + n0 + c4 * 4) = nf;
        }
        return;
    }

    // GEMM1: truncate K-trip to cover only nonzero P columns (bit-exact).
    int kiters = KITERS;
    if (!MASK && klen > 0) {
        int needed = (klen + 63) >> 6;
        kiters = needed < KITERS ? needed : KITERS;
    }

    Ah += (size_t)b * 2048 * KDIM + (size_t)m0 * KDIM;
    Al += (size_t)b * 2048 * KDIM + (size_t)m0 * KDIM;
    Bh += (size_t)b * NTOT * KDIM + (size_t)n0 * KDIM;
    Bl += (size_t)b * NTOT * KDIM + (size_t)n0 * KDIM;

    float acc[4][4][4];
#pragma unroll
    for (int i = 0; i < 4; i++)
#pragma unroll
        for (int j = 0; j < 4; j++)
#pragma unroll
            for (int k = 0; k < 4; k++) acc[i][j][k] = 0.0f;

    // ldmatrix per-lane address components (smem row&7 == lane&7 for all tiles)
    const int lrow = lane & 7, sub = lane >> 3;
    const uint32_t roff = (uint32_t)((lrow + ((sub & 1) << 3)) << 7);
    const int kx = sub >> 1;
    const int swz = lrow;

    // Prologue: stages 0 and 1 in flight (stage1 load may be past kiters; it
    // reads in-bounds memory and is simply never consumed in that case).
    load_stage_fn<KDIM>(sb,            Ah, Al, Bh, Bl, 0,  tid);
    CP_COMMIT();
    load_stage_fn<KDIM>(sb + STAGE_B,  Ah, Al, Bh, Bl, 64, tid);
    CP_COMMIT();

    Frags fr[2];
    for (int it = 0; it < kiters; ++it) {
        CP_WAIT1();            // stage it complete (it+1 may pend)
        __syncthreads();       // everyone done reading stage (it+2)%3 from iter it-1
        if (it + 2 < kiters)
            load_stage_fn<KDIM>(sb + ((it + 2) % 3) * STAGE_B, Ah, Al, Bh, Bl,
                                (it + 2) * 64, tid);
        CP_COMMIT();           // commit (possibly empty) to keep group accounting

        const uint32_t aB = sb + (uint32_t)((it % 3) * STAGE_B);
        const uint32_t bB = aB + 32768u;

        load_frags(fr[0], aB, bB, 0, roff, kx, swz, wm, wn);
#pragma unroll
        for (int ks = 0; ks < 4; ++ks) {
            if (ks < 3)
                load_frags(fr[(ks + 1) & 1], aB, bB, ks + 1, roff, kx, swz, wm, wn);
            mma_all(acc, fr[ks & 1]);
        }
    }

    // Epilogue: direct float2 stores (sector-aligned), mask for GEMM0
    const int kl = MASK ? klen : 0x7fffffff;
#pragma unroll
    for (int i = 0; i < 4; i++) {
        const int r = m0 + wm * 64 + i * 16 + (lane >> 2);
#pragma unroll
        for (int j = 0; j < 4; j++) {
            const int col = n0 + wn * 32 + j * 8 + ((lane & 3) << 1);
            float2 v0 = make_float2(acc[i][j][0], acc[i][j][1]);
            float2 v1 = make_float2(acc[i][j][2], acc[i][j][3]);
            if (MASK) {
                if (col     >= kl) { v0.x = NEG_INF; v1.x = NEG_INF; }
                if (col + 1 >= kl) { v0.y = NEG_INF; v1.y = NEG_INF; }
            }
            *(float2*)(C + (size_t)r * NTOT + col) = v0;
            *(float2*)(C + (size_t)(r + 8) * NTOT + col) = v1;
        }
    }
}

// ---------------------------------------------------------------------------
extern "C" void kernel_launch(void* const* d_in, const int* in_sizes, int n_in,
                              void* d_out, int out_size) {
    const float* Q      = (const float*)d_in[0];
    const float* K      = (const float*)d_in[1];
    const float* V      = (const float*)d_in[2];
    const int*  key_len = (const int*)d_in[3];
    float* Out = (float*)d_out;

    cudaFuncSetAttribute(gemm_mma<0>, cudaFuncAttributeMaxDynamicSharedMemorySize, SMEM_BYTES);
    cudaFuncSetAttribute(gemm_mma<1>, cudaFuncAttributeMaxDynamicSharedMemorySize, SMEM_BYTES);

    const int n4 = Bc * LQ * DD / 4;    // 8388608
    split_hl<0><<<(n4 + 255) / 256, 256>>>((const float4*)Q, n4);
    split_hl<1><<<(n4 + 255) / 256, 256>>>((const float4*)K, n4);

    dim3 gt(DD / 32, LK / 32, Bc);
    transpose_split_v<<<gt, dim3(32, 8)>>>(V);

    dim3 g1(LK / 128, LQ / 128, Bc);    // (16,16,16)
    gemm_mma<0><<<g1, 256, SMEM_BYTES>>>(nullptr, key_len);

    dim3 g2(LQ, Bc);
    softmax_split<<<g2, 256>>>();

    dim3 g3(DD / 128, LQ / 128, Bc);    // (8,16,16)
    gemm_mma<1><<<g3, 256, SMEM_BYTES>>>(Out, key_len);
}